// round 2
// baseline (speedup 1.0000x reference)
#include <cuda_runtime.h>
#include <cuda_bf16.h>
#include <math.h>

// ----------------------------------------------------------------------------
// SpectralLoss on GB300.
//   rain_hr: (16, 8, 1, 512, 512) f32
//   1) mean over T=8                         (fused into row-FFT kernel)
//   2) fft2 per (b) image, |.|^2
//   3) sum over b, radial binning (centered radius grid on UNSHIFTED fft)
//   4) normalized MSE vs k^{-5/3} reference  -> scalar
//
// K1: per (b,row): load 8 frames' row, average, 512-pt FFT (radix-2 DIT,
//     bit-reversed shared input), write complex row to g_fft.
// K2: per (b, 16-column group): load 512x16 complex tile (coalesced 128B row
//     segments), 16 column FFTs in shared, power + radial bins into shared,
//     write 256 partial bins per block (plus geometry counts for b==0 blocks).
// K3: single block: combine partials deterministically, compute loss scalar.
// ----------------------------------------------------------------------------

#define N512 512
#define NB   16          // images (B*C)
#define NT   8

__device__ float2 g_fft[(size_t)NB * N512 * N512];   // 32 MB scratch
__device__ float  g_part[512 * 512];                 // [block][256 power | 256 count]

__device__ __forceinline__ float2 cmul(float2 a, float2 b) {
    return make_float2(a.x * b.x - a.y * b.y, a.x * b.y + a.y * b.x);
}

// ---------------- K1: T-mean + row FFT -----------------
__global__ __launch_bounds__(256) void k_mean_rowfft(const float* __restrict__ in) {
    __shared__ float2 sh[N512];
    __shared__ float2 tw[256];
    const int tid = threadIdx.x;
    const int b   = blockIdx.x >> 9;
    const int h   = blockIdx.x & 511;

    // twiddle table: tw[k] = exp(-2*pi*i*k/512), k in [0,256)
    {
        float ang = -6.283185307179586f * (float)tid / 512.0f;
        float s, c;
        sincosf(ang, &s, &c);
        tw[tid] = make_float2(c, s);
    }

    // mean over T=8 frames for this (b,h) row; coalesced over w
    const float* base = in + ((size_t)b * NT * N512 + h) * N512;
    float a0 = 0.f, a1 = 0.f;
#pragma unroll
    for (int t = 0; t < NT; t++) {
        a0 += base[(size_t)t * (N512 * N512) + tid];
        a1 += base[(size_t)t * (N512 * N512) + tid + 256];
    }
    a0 *= 0.125f;
    a1 *= 0.125f;

    // bit-reversed placement (9 bits)
    sh[__brev((unsigned)tid)        >> 23] = make_float2(a0, 0.f);
    sh[__brev((unsigned)(tid + 256)) >> 23] = make_float2(a1, 0.f);
    __syncthreads();

    // radix-2 DIT, 9 stages, one butterfly per thread per stage
#pragma unroll
    for (int s = 1; s <= 9; s++) {
        const int half = 1 << (s - 1);
        const int j    = tid & (half - 1);
        const int bi   = ((tid >> (s - 1)) << s) + j;
        float2 w  = tw[j << (9 - s)];
        float2 u  = sh[bi];
        float2 wv = cmul(sh[bi + half], w);
        sh[bi]        = make_float2(u.x + wv.x, u.y + wv.y);
        sh[bi + half] = make_float2(u.x - wv.x, u.y - wv.y);
        __syncthreads();
    }

    float2* out = g_fft + ((size_t)b * N512 + h) * N512;
    out[tid]       = sh[tid];
    out[tid + 256] = sh[tid + 256];
}

// ---------------- K2: column FFT on 16-column tiles + radial binning ---------
// dynamic smem layout: tile[512*16] float2 | tw[256] float2 | pbins[256] | pcnt[256]
__global__ __launch_bounds__(256) void k_colfft_bin() {
    extern __shared__ float2 smem[];
    float2* tile = smem;                   // 8192 float2 = 64 KB
    float2* tw   = smem + 8192;            // 256 float2  = 2 KB
    float*  pb   = (float*)(tw + 256);     // 256 f
    float*  pc   = pb + 256;               // 256 f

    const int tid = threadIdx.x;
    const int b   = blockIdx.x >> 5;       // image
    const int cg  = blockIdx.x & 31;       // column group
    const int c0  = cg << 4;

    {
        float ang = -6.283185307179586f * (float)tid / 512.0f;
        float s, c;
        sincosf(ang, &s, &c);
        tw[tid] = make_float2(c, s);
    }
    pb[tid] = 0.f;
    pc[tid] = 0.f;

    // load 512x16 tile, rows bit-reversed into shared. Each 16-lane group
    // reads one contiguous 128B row segment -> fully coalesced.
    const float2* src = g_fft + (size_t)b * (N512 * N512);
    for (int i = tid; i < 512 * 16; i += 256) {
        int row  = i >> 4;
        int col  = i & 15;
        int rrow = __brev((unsigned)row) >> 23;
        tile[rrow * 16 + col] = src[(size_t)row * N512 + c0 + col];
    }
    __syncthreads();

    const int col  = tid & 15;
    const int slot = tid >> 4;   // 16 threads per column, 16 butterflies each

    for (int s = 1; s <= 9; s++) {
        const int half = 1 << (s - 1);
#pragma unroll
        for (int k = 0; k < 16; k++) {
            int t  = slot + (k << 4);              // butterfly id 0..255
            int j  = t & (half - 1);
            int bi = ((t >> (s - 1)) << s) + j;
            float2 w  = tw[j << (9 - s)];
            float2 u  = tile[bi * 16 + col];
            float2 wv = cmul(tile[(bi + half) * 16 + col], w);
            tile[bi * 16 + col]          = make_float2(u.x + wv.x, u.y + wv.y);
            tile[(bi + half) * 16 + col] = make_float2(u.x - wv.x, u.y - wv.y);
        }
        __syncthreads();
    }

    // power + radial binning.  radius = int(sqrt((ky-256)^2 + (kx-256)^2)),
    // exact-integer float -> __fsqrt_rn matches the f32 reference truncation.
    const bool count_blk = (b == 0);
    for (int i = tid; i < 512 * 16; i += 256) {
        int row = i >> 4;
        int c   = i & 15;
        float2 v = tile[row * 16 + c];
        float  p = v.x * v.x + v.y * v.y;
        int dy = row - 256;
        int dx = c0 + c - 256;
        int rr = (int)__fsqrt_rn((float)(dy * dy + dx * dx));
        if (rr < 256) {
            atomicAdd(&pb[rr], p);
            if (count_blk) atomicAdd(&pc[rr], 1.0f);
        }
    }
    __syncthreads();

    g_part[blockIdx.x * 512 + tid] = pb[tid];
    if (count_blk) g_part[blockIdx.x * 512 + 256 + tid] = pc[tid];
}

// ---------------- K3: final scalar ----------------
__global__ __launch_bounds__(256) void k_final(float* __restrict__ out) {
    __shared__ float seg[256];
    __shared__ float cnt[256];
    const int tid = threadIdx.x;

    float s = 0.f;
    for (int blk = 0; blk < 512; blk++) s += g_part[blk * 512 + tid];
    seg[tid] = s;

    float c = 0.f;
    for (int blk = 0; blk < 32; blk++) c += g_part[blk * 512 + 256 + tid];
    cnt[tid] = c;
    __syncthreads();

    if (tid == 0) {
        float gen[256], refv[256];
        float gsum = 0.f, rsum = 0.f;
        for (int r = 1; r < 256; r++) {
            float cr    = cnt[r];
            float denom = fmaxf(cr, 1.0f) * (float)NB;
            float g     = (cr > 0.f) ? seg[r] / denom : 0.f;
            gen[r] = g;
            gsum  += g;
            float rk = powf((float)r, -5.0f / 3.0f);
            refv[r] = rk;
            rsum   += rk;
        }
        float gs = gsum + 1e-8f;
        float rs = rsum + 1e-8f;
        float loss = 0.f;
        for (int r = 1; r < 256; r++) {
            float d = gen[r] / gs - refv[r] / rs;
            loss += d * d;
        }
        out[0] = loss / 255.0f;
    }
}

extern "C" void kernel_launch(void* const* d_in, const int* in_sizes, int n_in,
                              void* d_out, int out_size) {
    (void)in_sizes; (void)n_in; (void)out_size;
    const float* in  = (const float*)d_in[0];
    float*       out = (float*)d_out;

    k_mean_rowfft<<<NB * N512, 256>>>(in);

    const int smem = (512 * 16 + 256) * (int)sizeof(float2) + 512 * (int)sizeof(float); // 69632
    cudaFuncSetAttribute(k_colfft_bin, cudaFuncAttributeMaxDynamicSharedMemorySize, smem);
    k_colfft_bin<<<NB * 32, 256, smem>>>();

    k_final<<<1, 256>>>(out);
}

// round 3
// speedup vs baseline: 1.2386x; 1.2386x over previous
#include <cuda_runtime.h>
#include <cuda_bf16.h>
#include <math.h>

// ----------------------------------------------------------------------------
// SpectralLoss on GB300 — Hermitian-symmetry version.
//   rain_hr: (16, 8, 1, 512, 512) f32, real input.
//
// K1: per (b, row-pair): T-mean of rows 2h and 2h+1, pack as complex, one
//     512-pt radix-2 FFT, Hermitian split -> store spectra for k=0..256 only.
// K2: per (b, 16-col group over kx=0..256): column FFTs on padded shared tile,
//     power with mirror weight (2 for 1..255, 1 for 0/256), radial bins.
// K3: single block deterministic combine + loss scalar.
// ----------------------------------------------------------------------------

#define N512 512
#define NB   16
#define NT   8
#define RS   264                 // g_fft row stride (float2), 257 used
#define TILE_S 17                // padded tile stride (float2) to break conflicts
#define K2_GRID (NB * 17)        // 17 column groups cover kx 0..271 (mask >256)

__device__ float2 g_fft[(size_t)NB * N512 * RS];   // ~17.3 MB scratch
__device__ float  g_part[K2_GRID * 512];           // [block][256 pow | 256 cnt]

__device__ __forceinline__ float2 cmul(float2 a, float2 b) {
    return make_float2(a.x * b.x - a.y * b.y, a.x * b.y + a.y * b.x);
}

// ---------------- K1: T-mean of a row pair + one complex FFT -----------------
__global__ __launch_bounds__(256) void k_mean_rowfft(const float* __restrict__ in) {
    __shared__ float2 sh[N512];
    __shared__ float2 tw[256];
    const int tid = threadIdx.x;
    const int b   = blockIdx.x >> 8;        // image
    const int hp  = blockIdx.x & 255;       // row pair -> rows 2hp, 2hp+1

    {
        float ang = -6.283185307179586f * (float)tid / 512.0f;
        float s, c;
        sincosf(ang, &s, &c);
        tw[tid] = make_float2(c, s);
    }

    // mean over T for both rows; real row -> re, odd row -> im
    const float* base = in + ((size_t)b * NT * N512 + 2 * hp) * N512;
    float a0 = 0.f, a1 = 0.f, c0 = 0.f, c1 = 0.f;
#pragma unroll
    for (int t = 0; t < NT; t++) {
        const float* p = base + (size_t)t * (N512 * N512);
        a0 += p[tid];
        a1 += p[tid + 256];
        c0 += p[N512 + tid];
        c1 += p[N512 + tid + 256];
    }
    a0 *= 0.125f; a1 *= 0.125f; c0 *= 0.125f; c1 *= 0.125f;

    sh[__brev((unsigned)tid)         >> 23] = make_float2(a0, c0);
    sh[__brev((unsigned)(tid + 256)) >> 23] = make_float2(a1, c1);
    __syncthreads();

#pragma unroll
    for (int s = 1; s <= 9; s++) {
        const int half = 1 << (s - 1);
        const int j    = tid & (half - 1);
        const int bi   = ((tid >> (s - 1)) << s) + j;
        float2 w  = tw[j << (9 - s)];
        float2 u  = sh[bi];
        float2 wv = cmul(sh[bi + half], w);
        sh[bi]        = make_float2(u.x + wv.x, u.y + wv.y);
        sh[bi + half] = make_float2(u.x - wv.x, u.y - wv.y);
        __syncthreads();
    }

    // Hermitian split: Z = Fe + i*Fo ->
    //   Fe[k] = (Z[k] + conj(Z[-k]))/2,  Fo[k] = (Z[k] - conj(Z[-k]))/(2i)
    float2* oute = g_fft + ((size_t)b * N512 + 2 * hp) * RS;
    float2* outo = oute + RS;
    for (int k = tid; k <= 256; k += 256) {
        int m = (N512 - k) & (N512 - 1);
        float2 zk = sh[k], zm = sh[m];
        oute[k] = make_float2(0.5f * (zk.x + zm.x), 0.5f * (zk.y - zm.y));
        outo[k] = make_float2(0.5f * (zk.y + zm.y), 0.5f * (zm.x - zk.x));
    }
}

// ---------------- K2: column FFT + weighted radial binning -------------------
// dyn smem: tile[512*17] f2 | tw[256] f2 | pb[256] f | pc[256] f  = 73728 B
__global__ __launch_bounds__(256) void k_colfft_bin() {
    extern __shared__ float2 smem[];
    float2* tile = smem;                     // 512*17 float2
    float2* tw   = smem + N512 * TILE_S;
    float*  pb   = (float*)(tw + 256);
    float*  pc   = pb + 256;

    const int tid = threadIdx.x;
    const int b   = blockIdx.x / 17;
    const int g   = blockIdx.x % 17;
    const int cb  = g << 4;                  // first kx of this group

    {
        float ang = -6.283185307179586f * (float)tid / 512.0f;
        float s, c;
        sincosf(ang, &s, &c);
        tw[tid] = make_float2(c, s);
    }
    pb[tid] = 0.f;
    pc[tid] = 0.f;

    const float2* src = g_fft + (size_t)b * (N512 * RS);
    for (int i = tid; i < N512 * 16; i += 256) {
        int row  = i >> 4;
        int col  = i & 15;
        int kx   = cb + col;
        int rrow = __brev((unsigned)row) >> 23;
        tile[rrow * TILE_S + col] =
            (kx <= 256) ? src[(size_t)row * RS + kx] : make_float2(0.f, 0.f);
    }
    __syncthreads();

    const int col  = tid & 15;
    const int slot = tid >> 4;

    for (int s = 1; s <= 9; s++) {
        const int half = 1 << (s - 1);
#pragma unroll
        for (int k = 0; k < 16; k++) {
            int t  = slot + (k << 4);
            int j  = t & (half - 1);
            int bi = ((t >> (s - 1)) << s) + j;
            float2 w  = tw[j << (9 - s)];
            float2 u  = tile[bi * TILE_S + col];
            float2 wv = cmul(tile[(bi + half) * TILE_S + col], w);
            tile[bi * TILE_S + col]          = make_float2(u.x + wv.x, u.y + wv.y);
            tile[(bi + half) * TILE_S + col] = make_float2(u.x - wv.x, u.y - wv.y);
        }
        __syncthreads();
    }

    // weighted power + radial binning (mirror column 512-kx folded in)
    const bool count_blk = (b == 0);
    for (int i = tid; i < N512 * 16; i += 256) {
        int row = i >> 4;
        int c   = i & 15;
        int kx  = cb + c;
        if (kx > 256) continue;
        float w  = (kx == 0 || kx == 256) ? 1.0f : 2.0f;
        float2 v = tile[row * TILE_S + c];
        float  p = w * (v.x * v.x + v.y * v.y);
        int dy = row - 256;
        int dx = kx - 256;
        int rr = (int)__fsqrt_rn((float)(dy * dy + dx * dx));
        if (rr < 256) {
            atomicAdd(&pb[rr], p);
            if (count_blk) atomicAdd(&pc[rr], w);
        }
    }
    __syncthreads();

    g_part[blockIdx.x * 512 + tid] = pb[tid];
    if (count_blk) g_part[blockIdx.x * 512 + 256 + tid] = pc[tid];
}

// ---------------- K3: final scalar ----------------
__global__ __launch_bounds__(256) void k_final(float* __restrict__ out) {
    __shared__ float seg[256];
    __shared__ float cnt[256];
    const int tid = threadIdx.x;

    float s = 0.f;
    for (int blk = 0; blk < K2_GRID; blk++) s += g_part[blk * 512 + tid];
    seg[tid] = s;

    float c = 0.f;
    for (int blk = 0; blk < 17; blk++) c += g_part[blk * 512 + 256 + tid];
    cnt[tid] = c;
    __syncthreads();

    if (tid == 0) {
        float gen[256], refv[256];
        float gsum = 0.f, rsum = 0.f;
        for (int r = 1; r < 256; r++) {
            float cr    = cnt[r];
            float denom = fmaxf(cr, 1.0f) * (float)NB;
            float g     = (cr > 0.f) ? seg[r] / denom : 0.0f;
            gen[r] = g;
            gsum  += g;
            float rk = powf((float)r, -5.0f / 3.0f);
            refv[r] = rk;
            rsum   += rk;
        }
        float gs = gsum + 1e-8f;
        float rs = rsum + 1e-8f;
        float loss = 0.f;
        for (int r = 1; r < 256; r++) {
            float d = gen[r] / gs - refv[r] / rs;
            loss += d * d;
        }
        out[0] = loss / 255.0f;
    }
}

extern "C" void kernel_launch(void* const* d_in, const int* in_sizes, int n_in,
                              void* d_out, int out_size) {
    (void)in_sizes; (void)n_in; (void)out_size;
    const float* in  = (const float*)d_in[0];
    float*       out = (float*)d_out;

    k_mean_rowfft<<<NB * 256, 256>>>(in);

    const int smem = (N512 * TILE_S + 256) * (int)sizeof(float2) + 512 * (int)sizeof(float);
    cudaFuncSetAttribute(k_colfft_bin, cudaFuncAttributeMaxDynamicSharedMemorySize, smem);
    k_colfft_bin<<<K2_GRID, 256, smem>>>();

    k_final<<<1, 256>>>(out);
}

// round 4
// speedup vs baseline: 1.8764x; 1.5149x over previous
#include <cuda_runtime.h>
#include <cuda_bf16.h>
#include <math.h>

// ----------------------------------------------------------------------------
// SpectralLoss on GB300 — register radix-8 FFT version.
//   512-pt FFT = 3 radix-8 stages; 64 threads/FFT, 8 complex regs/thread,
//   2 bank-conflict-free shared exchanges (pad 8/64 + XOR swizzle).
// K1: T-mean + packed row-pair FFT + Hermitian split -> g_fft[k=0..256].
// K2: column FFT (4 cols/block) + weighted radial binning -> partials.
// k_reduce: per-bin combine (256 blocks). k_final: loss scalar.
// ----------------------------------------------------------------------------

#define N512 512
#define NB   16
#define NT   8
#define RS   264                  // g_fft row stride (float2)
#define K2_BLOCKS (NB * 65)       // 1040
#define PART_STRIDE 1056
#define CNT_STRIDE  72
#define FPAD(i) ((i) + (((i) >> 6) << 3))   // +8 pad per 64 slots

__device__ float2 g_fft[(size_t)NB * N512 * RS];     // ~17.3 MB
__device__ float  g_part[256 * PART_STRIDE];
__device__ float  g_cnt [256 * CNT_STRIDE];
__device__ float  g_seg2[256];
__device__ float  g_cnt2[256];

__device__ __forceinline__ float2 cadd(float2 a, float2 b){ return make_float2(a.x+b.x, a.y+b.y); }
__device__ __forceinline__ float2 csub(float2 a, float2 b){ return make_float2(a.x-b.x, a.y-b.y); }
__device__ __forceinline__ float2 cmul(float2 a, float2 b){
    return make_float2(a.x*b.x - a.y*b.y, a.x*b.y + a.y*b.x);
}
__device__ __forceinline__ float2 mul_mi(float2 a){ return make_float2(a.y, -a.x); }        // * -i
__device__ __forceinline__ float2 mul_w81(float2 a){                                         // * (1-i)/sqrt2
    const float C = 0.70710678118654752f;
    return make_float2(C*(a.x+a.y), C*(a.y-a.x));
}
__device__ __forceinline__ float2 mul_w83(float2 a){                                         // * (-1-i)/sqrt2
    const float C = 0.70710678118654752f;
    return make_float2(C*(a.y-a.x), -C*(a.x+a.y));
}

// natural-order 8-point DFT (DIF), X[k] = sum a[n] W8^{nk}
__device__ __forceinline__ void dft8(const float2* a, float2* X){
    float2 t0 = cadd(a[0], a[4]), t1 = cadd(a[1], a[5]);
    float2 t2 = cadd(a[2], a[6]), t3 = cadd(a[3], a[7]);
    float2 u0 = csub(a[0], a[4]);
    float2 u1 = mul_w81(csub(a[1], a[5]));
    float2 u2 = mul_mi (csub(a[2], a[6]));
    float2 u3 = mul_w83(csub(a[3], a[7]));
    float2 s0 = cadd(t0, t2), s1 = cadd(t1, t3);
    float2 d0 = csub(t0, t2), d1 = mul_mi(csub(t1, t3));
    float2 e0 = cadd(u0, u2), e1 = cadd(u1, u3);
    float2 f0 = csub(u0, u2), f1 = mul_mi(csub(u1, u3));
    X[0] = cadd(s0, s1); X[4] = csub(s0, s1);
    X[2] = cadd(d0, d1); X[6] = csub(d0, d1);
    X[1] = cadd(e0, e1); X[5] = csub(e0, e1);
    X[3] = cadd(f0, f1); X[7] = csub(f0, f1);
}

// stage 1: a[p] = x[t + 64p] -> y_q[t] = DFT8_p(a) * W512^{tq}, stored at 72q+t
__device__ __forceinline__ void fft_stage1(const float2* a, int t, float* sre, float* sim){
    float2 b[8];
    dft8(a, b);
    float ang = -6.2831853071795864f * (float)t / 512.0f;
    float2 w1; sincosf(ang, &w1.y, &w1.x);
    sre[t] = b[0].x; sim[t] = b[0].y;
    float2 wp = w1;
#pragma unroll
    for (int q = 1; q < 8; q++){
        float2 c = cmul(b[q], wp);
        sre[72*q + t] = c.x; sim[72*q + t] = c.y;
        wp = cmul(wp, w1);
    }
}

// stages 2+3: consumes y in shared, returns X[w] at ky = ky0 + 64w
__device__ __forceinline__ void fft_stage23(float* sre, float* sim, int t,
                                            float2* X, int* ky0_out){
    const int q = t >> 3, u = t & 7;
    float2 a[8], b[8];
#pragma unroll
    for (int v = 0; v < 8; v++){
        int idx = 72*q + u + 8*v;
        a[v] = make_float2(sre[idx], sim[idx]);
    }
    dft8(a, b);
    float ang = -6.2831853071795864f * (float)u / 64.0f;
    float2 w1; sincosf(ang, &w1.y, &w1.x);
    __syncwarp();
    {   // r = 0 (no twiddle)
        int idx = 72*q + (u ^ ((2*q) & 7));
        sre[idx] = b[0].x; sim[idx] = b[0].y;
    }
    float2 wp = w1;
#pragma unroll
    for (int r = 1; r < 8; r++){
        float2 c = cmul(b[r], wp);
        int swz = (2*q + (r >> 2)) & 7;
        int idx = 72*q + 8*r + (u ^ swz);
        sre[idx] = c.x; sim[idx] = c.y;
        wp = cmul(wp, w1);
    }
    __syncwarp();
    const int r3 = u;
    const int swz = (2*q + (r3 >> 2)) & 7;
#pragma unroll
    for (int uu = 0; uu < 8; uu++){
        int idx = 72*q + 8*r3 + (uu ^ swz);
        a[uu] = make_float2(sre[idx], sim[idx]);
    }
    dft8(a, X);
    *ky0_out = q + 8*r3;
}

// ---------------- K1: T-mean + packed row-pair FFT + Hermitian split ---------
__global__ __launch_bounds__(256) void k_mean_rowfft(const float* __restrict__ in){
    __shared__ float sre[4][584], sim[4][584];
    const int tid  = threadIdx.x;
    const int team = tid >> 6;
    const int t    = tid & 63;
    const int b    = blockIdx.x >> 6;
    const int hp   = ((blockIdx.x & 63) << 2) + team;    // row pair 0..255

    const float* base = in + ((size_t)b * NT * N512 + 2 * hp) * N512;
    float2 a[8];
#pragma unroll
    for (int p = 0; p < 8; p++) a[p] = make_float2(0.f, 0.f);
#pragma unroll
    for (int tt = 0; tt < NT; tt++){
        const float* pe = base + (size_t)tt * (N512 * N512);
#pragma unroll
        for (int p = 0; p < 8; p++){
            a[p].x += pe[t + 64*p];            // even row -> re
            a[p].y += pe[N512 + t + 64*p];     // odd row  -> im
        }
    }
#pragma unroll
    for (int p = 0; p < 8; p++){ a[p].x *= 0.125f; a[p].y *= 0.125f; }

    fft_stage1(a, t, sre[team], sim[team]);
    __syncthreads();
    float2 X[8]; int ky0;
    fft_stage23(sre[team], sim[team], t, X, &ky0);
    __syncthreads();
#pragma unroll
    for (int w = 0; w < 8; w++){
        sre[team][ky0 + 72*w] = X[w].x;        // = FPAD(ky0 + 64w)
        sim[team][ky0 + 72*w] = X[w].y;
    }
    __syncthreads();

    // Hermitian split: Z = Fe + i*Fo
    float2* oute = g_fft + ((size_t)b * N512 + 2 * hp) * RS;
    float2* outo = oute + RS;
    for (int k = t; k <= 256; k += 64){
        int m = (N512 - k) & (N512 - 1);
        float2 zk = make_float2(sre[team][FPAD(k)], sim[team][FPAD(k)]);
        float2 zm = make_float2(sre[team][FPAD(m)], sim[team][FPAD(m)]);
        oute[k] = make_float2(0.5f*(zk.x + zm.x), 0.5f*(zk.y - zm.y));
        outo[k] = make_float2(0.5f*(zk.y + zm.y), 0.5f*(zm.x - zk.x));
    }
}

// ---------------- K2: column FFT (4 cols/block) + radial binning -------------
__global__ __launch_bounds__(256) void k_colfft_bin(){
    __shared__ float sre[4][584], sim[4][584];
    __shared__ float pb[256], pc[256];
    const int tid = threadIdx.x;
    const int b   = blockIdx.x / 65;
    const int g   = blockIdx.x % 65;
    const int kx0 = g << 2;

    pb[tid] = 0.f; pc[tid] = 0.f;

    // coop load: 512 rows x 4 columns; full 32B sectors, each element read once
    const float2* src = g_fft + (size_t)b * (N512 * RS);
#pragma unroll
    for (int k = 0; k < 8; k++){
        int idx = tid + (k << 8);
        int row = idx >> 2, c = idx & 3;
        int kx  = kx0 + c;
        float2 v = (kx <= 256) ? src[(size_t)row * RS + kx] : make_float2(0.f, 0.f);
        sre[c][FPAD(row)] = v.x; sim[c][FPAD(row)] = v.y;
    }
    __syncthreads();

    const int team = tid >> 6, t = tid & 63;
    float2 a[8];
#pragma unroll
    for (int p = 0; p < 8; p++)
        a[p] = make_float2(sre[team][t + 72*p], sim[team][t + 72*p]);  // FPAD(t+64p)
    fft_stage1(a, t, sre[team], sim[team]);     // in-place safe: slot set {72j+t} per thread
    __syncthreads();
    float2 X[8]; int ky0;
    fft_stage23(sre[team], sim[team], t, X, &ky0);

    const int kx = kx0 + team;
    if (kx <= 256){
        float wgt = (kx == 0 || kx == 256) ? 1.f : 2.f;   // mirror column folded in
        int   dx  = kx - 256;
        float fdx2 = (float)(dx * dx);
        const bool cblk = (b == 0);
#pragma unroll
        for (int w = 0; w < 8; w++){
            int   ky = ky0 + (w << 6);
            float p  = wgt * (X[w].x * X[w].x + X[w].y * X[w].y);
            int   dy = ky - 256;
            int   rr = (int)__fsqrt_rn((float)(dy * dy) + fdx2);
            if (rr < 256){
                atomicAdd(&pb[rr], p);
                if (cblk) atomicAdd(&pc[rr], wgt);
            }
        }
    }
    __syncthreads();
    g_part[tid * PART_STRIDE + blockIdx.x] = pb[tid];
    if (b == 0) g_cnt[tid * CNT_STRIDE + g] = pc[tid];
}

// ---------------- reduce: one block per radial bin ----------------
__global__ __launch_bounds__(256) void k_reduce(){
    __shared__ float red[256];
    const int bin = blockIdx.x, tid = threadIdx.x;
    float s = 0.f;
    for (int blk = tid; blk < K2_BLOCKS; blk += 256)
        s += g_part[bin * PART_STRIDE + blk];
    red[tid] = s; __syncthreads();
    for (int o = 128; o > 0; o >>= 1){ if (tid < o) red[tid] += red[tid + o]; __syncthreads(); }
    if (tid == 0) g_seg2[bin] = red[0];
    __syncthreads();
    red[tid] = (tid < 65) ? g_cnt[bin * CNT_STRIDE + tid] : 0.f;
    __syncthreads();
    for (int o = 128; o > 0; o >>= 1){ if (tid < o) red[tid] += red[tid + o]; __syncthreads(); }
    if (tid == 0) g_cnt2[bin] = red[0];
}

// ---------------- final scalar ----------------
__global__ __launch_bounds__(256) void k_final(float* __restrict__ out){
    __shared__ float seg[256], cnt[256];
    const int tid = threadIdx.x;
    seg[tid] = g_seg2[tid];
    cnt[tid] = g_cnt2[tid];
    __syncthreads();
    if (tid == 0){
        float gen[256], refv[256];
        float gsum = 0.f, rsum = 0.f;
        for (int r = 1; r < 256; r++){
            float cr    = cnt[r];
            float denom = fmaxf(cr, 1.0f) * (float)NB;
            float gv    = (cr > 0.f) ? seg[r] / denom : 0.0f;
            gen[r] = gv; gsum += gv;
            float rk = powf((float)r, -5.0f / 3.0f);
            refv[r] = rk; rsum += rk;
        }
        float gs = gsum + 1e-8f;
        float rs = rsum + 1e-8f;
        float loss = 0.f;
        for (int r = 1; r < 256; r++){
            float d = gen[r] / gs - refv[r] / rs;
            loss += d * d;
        }
        out[0] = loss / 255.0f;
    }
}

extern "C" void kernel_launch(void* const* d_in, const int* in_sizes, int n_in,
                              void* d_out, int out_size) {
    (void)in_sizes; (void)n_in; (void)out_size;
    const float* in  = (const float*)d_in[0];
    float*       out = (float*)d_out;

    k_mean_rowfft<<<NB * 64, 256>>>(in);
    k_colfft_bin<<<K2_BLOCKS, 256>>>();
    k_reduce<<<256, 256>>>();
    k_final<<<1, 256>>>(out);
}

// round 5
// speedup vs baseline: 3.7594x; 2.0035x over previous
#include <cuda_runtime.h>
#include <cuda_bf16.h>
#include <math.h>

// ----------------------------------------------------------------------------
// SpectralLoss on GB300 — register radix-8 FFT + parallel epilogue.
//   512-pt FFT = 3 radix-8 stages; 64 threads/FFT, 8 complex regs/thread,
//   2 bank-conflict-free shared exchanges (pad 8/64 + XOR swizzle).
// K1: T-mean + packed row-pair FFT + Hermitian split -> g_fft[k=0..256].
// K2: column FFT (4 cols/block) + weighted radial binning -> partials.
// k_reduce: per-bin combine (256 blocks). k_final: parallel loss scalar.
// ----------------------------------------------------------------------------

#define N512 512
#define NB   16
#define NT   8
#define RS   264                  // g_fft row stride (float2)
#define K2_BLOCKS (NB * 65)       // 1040
#define PART_STRIDE 1056
#define CNT_STRIDE  72
#define FPAD(i) ((i) + (((i) >> 6) << 3))   // +8 pad per 64 slots

__device__ float2 g_fft[(size_t)NB * N512 * RS];     // ~17.3 MB
__device__ float  g_part[256 * PART_STRIDE];
__device__ float  g_cnt [256 * CNT_STRIDE];
__device__ float  g_seg2[256];
__device__ float  g_cnt2[256];

__device__ __forceinline__ float2 cadd(float2 a, float2 b){ return make_float2(a.x+b.x, a.y+b.y); }
__device__ __forceinline__ float2 csub(float2 a, float2 b){ return make_float2(a.x-b.x, a.y-b.y); }
__device__ __forceinline__ float2 cmul(float2 a, float2 b){
    return make_float2(a.x*b.x - a.y*b.y, a.x*b.y + a.y*b.x);
}
__device__ __forceinline__ float2 mul_mi(float2 a){ return make_float2(a.y, -a.x); }        // * -i
__device__ __forceinline__ float2 mul_w81(float2 a){                                         // * (1-i)/sqrt2
    const float C = 0.70710678118654752f;
    return make_float2(C*(a.x+a.y), C*(a.y-a.x));
}
__device__ __forceinline__ float2 mul_w83(float2 a){                                         // * (-1-i)/sqrt2
    const float C = 0.70710678118654752f;
    return make_float2(C*(a.y-a.x), -C*(a.x+a.y));
}

// natural-order 8-point DFT (DIF), X[k] = sum a[n] W8^{nk}
__device__ __forceinline__ void dft8(const float2* a, float2* X){
    float2 t0 = cadd(a[0], a[4]), t1 = cadd(a[1], a[5]);
    float2 t2 = cadd(a[2], a[6]), t3 = cadd(a[3], a[7]);
    float2 u0 = csub(a[0], a[4]);
    float2 u1 = mul_w81(csub(a[1], a[5]));
    float2 u2 = mul_mi (csub(a[2], a[6]));
    float2 u3 = mul_w83(csub(a[3], a[7]));
    float2 s0 = cadd(t0, t2), s1 = cadd(t1, t3);
    float2 d0 = csub(t0, t2), d1 = mul_mi(csub(t1, t3));
    float2 e0 = cadd(u0, u2), e1 = cadd(u1, u3);
    float2 f0 = csub(u0, u2), f1 = mul_mi(csub(u1, u3));
    X[0] = cadd(s0, s1); X[4] = csub(s0, s1);
    X[2] = cadd(d0, d1); X[6] = csub(d0, d1);
    X[1] = cadd(e0, e1); X[5] = csub(e0, e1);
    X[3] = cadd(f0, f1); X[7] = csub(f0, f1);
}

// stage 1: a[p] = x[t + 64p] -> y_q[t] = DFT8_p(a) * W512^{tq}, stored at 72q+t
__device__ __forceinline__ void fft_stage1(const float2* a, int t, float* sre, float* sim){
    float2 b[8];
    dft8(a, b);
    float ang = -6.2831853071795864f * (float)t / 512.0f;
    float2 w1; sincosf(ang, &w1.y, &w1.x);
    sre[t] = b[0].x; sim[t] = b[0].y;
    float2 wp = w1;
#pragma unroll
    for (int q = 1; q < 8; q++){
        float2 c = cmul(b[q], wp);
        sre[72*q + t] = c.x; sim[72*q + t] = c.y;
        wp = cmul(wp, w1);
    }
}

// stages 2+3: consumes y in shared, returns X[w] at ky = ky0 + 64w
__device__ __forceinline__ void fft_stage23(float* sre, float* sim, int t,
                                            float2* X, int* ky0_out){
    const int q = t >> 3, u = t & 7;
    float2 a[8], b[8];
#pragma unroll
    for (int v = 0; v < 8; v++){
        int idx = 72*q + u + 8*v;
        a[v] = make_float2(sre[idx], sim[idx]);
    }
    dft8(a, b);
    float ang = -6.2831853071795864f * (float)u / 64.0f;
    float2 w1; sincosf(ang, &w1.y, &w1.x);
    __syncwarp();
    {   // r = 0 (no twiddle)
        int idx = 72*q + (u ^ ((2*q) & 7));
        sre[idx] = b[0].x; sim[idx] = b[0].y;
    }
    float2 wp = w1;
#pragma unroll
    for (int r = 1; r < 8; r++){
        float2 c = cmul(b[r], wp);
        int swz = (2*q + (r >> 2)) & 7;
        int idx = 72*q + 8*r + (u ^ swz);
        sre[idx] = c.x; sim[idx] = c.y;
        wp = cmul(wp, w1);
    }
    __syncwarp();
    const int r3 = u;
    const int swz = (2*q + (r3 >> 2)) & 7;
#pragma unroll
    for (int uu = 0; uu < 8; uu++){
        int idx = 72*q + 8*r3 + (uu ^ swz);
        a[uu] = make_float2(sre[idx], sim[idx]);
    }
    dft8(a, X);
    *ky0_out = q + 8*r3;
}

// ---------------- K1: T-mean + packed row-pair FFT + Hermitian split ---------
__global__ __launch_bounds__(256) void k_mean_rowfft(const float* __restrict__ in){
    __shared__ float sre[4][584], sim[4][584];
    const int tid  = threadIdx.x;
    const int team = tid >> 6;
    const int t    = tid & 63;
    const int b    = blockIdx.x >> 6;
    const int hp   = ((blockIdx.x & 63) << 2) + team;    // row pair 0..255

    const float* base = in + ((size_t)b * NT * N512 + 2 * hp) * N512;
    float2 a[8];
#pragma unroll
    for (int p = 0; p < 8; p++) a[p] = make_float2(0.f, 0.f);
#pragma unroll
    for (int tt = 0; tt < NT; tt++){
        const float* pe = base + (size_t)tt * (N512 * N512);
#pragma unroll
        for (int p = 0; p < 8; p++){
            a[p].x += pe[t + 64*p];            // even row -> re
            a[p].y += pe[N512 + t + 64*p];     // odd row  -> im
        }
    }
#pragma unroll
    for (int p = 0; p < 8; p++){ a[p].x *= 0.125f; a[p].y *= 0.125f; }

    fft_stage1(a, t, sre[team], sim[team]);
    __syncthreads();
    float2 X[8]; int ky0;
    fft_stage23(sre[team], sim[team], t, X, &ky0);
    __syncthreads();
#pragma unroll
    for (int w = 0; w < 8; w++){
        sre[team][ky0 + 72*w] = X[w].x;        // = FPAD(ky0 + 64w)
        sim[team][ky0 + 72*w] = X[w].y;
    }
    __syncthreads();

    // Hermitian split: Z = Fe + i*Fo
    float2* oute = g_fft + ((size_t)b * N512 + 2 * hp) * RS;
    float2* outo = oute + RS;
    for (int k = t; k <= 256; k += 64){
        int m = (N512 - k) & (N512 - 1);
        float2 zk = make_float2(sre[team][FPAD(k)], sim[team][FPAD(k)]);
        float2 zm = make_float2(sre[team][FPAD(m)], sim[team][FPAD(m)]);
        oute[k] = make_float2(0.5f*(zk.x + zm.x), 0.5f*(zk.y - zm.y));
        outo[k] = make_float2(0.5f*(zk.y + zm.y), 0.5f*(zm.x - zk.x));
    }
}

// ---------------- K2: column FFT (4 cols/block) + radial binning -------------
__global__ __launch_bounds__(256) void k_colfft_bin(){
    __shared__ float sre[4][584], sim[4][584];
    __shared__ float pb[256], pc[256];
    const int tid = threadIdx.x;
    const int b   = blockIdx.x / 65;
    const int g   = blockIdx.x % 65;
    const int kx0 = g << 2;

    pb[tid] = 0.f; pc[tid] = 0.f;

    // coop load: 512 rows x 4 columns; full 32B sectors, each element read once
    const float2* src = g_fft + (size_t)b * (N512 * RS);
#pragma unroll
    for (int k = 0; k < 8; k++){
        int idx = tid + (k << 8);
        int row = idx >> 2, c = idx & 3;
        int kx  = kx0 + c;
        float2 v = (kx <= 256) ? src[(size_t)row * RS + kx] : make_float2(0.f, 0.f);
        sre[c][FPAD(row)] = v.x; sim[c][FPAD(row)] = v.y;
    }
    __syncthreads();

    const int team = tid >> 6, t = tid & 63;
    float2 a[8];
#pragma unroll
    for (int p = 0; p < 8; p++)
        a[p] = make_float2(sre[team][t + 72*p], sim[team][t + 72*p]);  // FPAD(t+64p)
    fft_stage1(a, t, sre[team], sim[team]);     // in-place safe: slot set {72j+t} per thread
    __syncthreads();
    float2 X[8]; int ky0;
    fft_stage23(sre[team], sim[team], t, X, &ky0);

    const int kx = kx0 + team;
    if (kx <= 256){
        float wgt = (kx == 0 || kx == 256) ? 1.f : 2.f;   // mirror column folded in
        int   dx  = kx - 256;
        float fdx2 = (float)(dx * dx);
        const bool cblk = (b == 0);
#pragma unroll
        for (int w = 0; w < 8; w++){
            int   ky = ky0 + (w << 6);
            float p  = wgt * (X[w].x * X[w].x + X[w].y * X[w].y);
            int   dy = ky - 256;
            int   rr = (int)__fsqrt_rn((float)(dy * dy) + fdx2);
            if (rr < 256){
                atomicAdd(&pb[rr], p);
                if (cblk) atomicAdd(&pc[rr], wgt);
            }
        }
    }
    __syncthreads();
    g_part[tid * PART_STRIDE + blockIdx.x] = pb[tid];
    if (b == 0) g_cnt[tid * CNT_STRIDE + g] = pc[tid];
}

// ---------------- reduce: one block per radial bin ----------------
__global__ __launch_bounds__(256) void k_reduce(){
    __shared__ float red[256];
    const int bin = blockIdx.x, tid = threadIdx.x;
    float s = 0.f;
    for (int blk = tid; blk < K2_BLOCKS; blk += 256)
        s += g_part[bin * PART_STRIDE + blk];
    red[tid] = s; __syncthreads();
    for (int o = 128; o > 0; o >>= 1){ if (tid < o) red[tid] += red[tid + o]; __syncthreads(); }
    if (tid == 0) g_seg2[bin] = red[0];
    __syncthreads();
    red[tid] = (tid < 65) ? g_cnt[bin * CNT_STRIDE + tid] : 0.f;
    __syncthreads();
    for (int o = 128; o > 0; o >>= 1){ if (tid < o) red[tid] += red[tid + o]; __syncthreads(); }
    if (tid == 0) g_cnt2[bin] = red[0];
}

// ---------------- final scalar: fully parallel over bins ----------------
__global__ __launch_bounds__(256) void k_final(float* __restrict__ out){
    __shared__ float red[256];
    __shared__ float s_gs, s_rs;
    const int tid = threadIdx.x;

    // per-bin values (bin r = tid, valid for 1..255)
    float gen = 0.f, refv = 0.f;
    if (tid >= 1){
        float cr    = g_cnt2[tid];
        float denom = fmaxf(cr, 1.0f) * (float)NB;
        gen  = (cr > 0.f) ? g_seg2[tid] / denom : 0.0f;
        refv = powf((float)tid, -5.0f / 3.0f);
    }

    // gsum
    red[tid] = gen; __syncthreads();
    for (int o = 128; o > 0; o >>= 1){ if (tid < o) red[tid] += red[tid + o]; __syncthreads(); }
    if (tid == 0) s_gs = red[0] + 1e-8f;
    __syncthreads();
    // rsum
    red[tid] = refv; __syncthreads();
    for (int o = 128; o > 0; o >>= 1){ if (tid < o) red[tid] += red[tid + o]; __syncthreads(); }
    if (tid == 0) s_rs = red[0] + 1e-8f;
    __syncthreads();

    float d = (tid >= 1) ? (gen / s_gs - refv / s_rs) : 0.f;
    red[tid] = d * d; __syncthreads();
    for (int o = 128; o > 0; o >>= 1){ if (tid < o) red[tid] += red[tid + o]; __syncthreads(); }
    if (tid == 0) out[0] = red[0] / 255.0f;
}

extern "C" void kernel_launch(void* const* d_in, const int* in_sizes, int n_in,
                              void* d_out, int out_size) {
    (void)in_sizes; (void)n_in; (void)out_size;
    const float* in  = (const float*)d_in[0];
    float*       out = (float*)d_out;

    k_mean_rowfft<<<NB * 64, 256>>>(in);
    k_colfft_bin<<<K2_BLOCKS, 256>>>();
    k_reduce<<<256, 256>>>();
    k_final<<<1, 256>>>(out);
}

// round 6
// speedup vs baseline: 3.8869x; 1.0339x over previous
#include <cuda_runtime.h>
#include <cuda_bf16.h>
#include <math.h>

// ----------------------------------------------------------------------------
// SpectralLoss on GB300 — register radix-8 FFT + fused reduction tail.
//   512-pt FFT = 3 radix-8 stages; 64 threads/FFT, 8 complex regs/thread,
//   2 bank-conflict-free shared exchanges (pad 8/64 + XOR swizzle).
// K1: T-mean + packed row-pair FFT + Hermitian split -> g_fft[k=0..256].
// K2: column FFT (4 cols/block) + weighted radial binning -> coalesced partials.
// K3 (k_reduce_final): per-bin combine; LAST arriving block computes the loss
//     scalar (int-atomic arrival counter -> deterministic), resets counter.
// ----------------------------------------------------------------------------

#define N512 512
#define NB   16
#define NT   8
#define RS   264                  // g_fft row stride (float2)
#define K2_BLOCKS (NB * 65)       // 1040
#define FPAD(i) ((i) + (((i) >> 6) << 3))   // +8 pad per 64 slots

__device__ float2 g_fft[(size_t)NB * N512 * RS];     // ~17.3 MB
__device__ float  g_part[K2_BLOCKS * 256];           // [block][bin]  (coalesced)
__device__ float  g_cnt [65 * 256];                  // [group][bin]
__device__ float  g_seg2[256];
__device__ float  g_cnt2[256];
__device__ unsigned g_arrive;                        // zero-init; reset each call

__device__ __forceinline__ float2 cadd(float2 a, float2 b){ return make_float2(a.x+b.x, a.y+b.y); }
__device__ __forceinline__ float2 csub(float2 a, float2 b){ return make_float2(a.x-b.x, a.y-b.y); }
__device__ __forceinline__ float2 cmul(float2 a, float2 b){
    return make_float2(a.x*b.x - a.y*b.y, a.x*b.y + a.y*b.x);
}
__device__ __forceinline__ float2 mul_mi(float2 a){ return make_float2(a.y, -a.x); }        // * -i
__device__ __forceinline__ float2 mul_w81(float2 a){                                         // * (1-i)/sqrt2
    const float C = 0.70710678118654752f;
    return make_float2(C*(a.x+a.y), C*(a.y-a.x));
}
__device__ __forceinline__ float2 mul_w83(float2 a){                                         // * (-1-i)/sqrt2
    const float C = 0.70710678118654752f;
    return make_float2(C*(a.y-a.x), -C*(a.x+a.y));
}

// natural-order 8-point DFT (DIF), X[k] = sum a[n] W8^{nk}
__device__ __forceinline__ void dft8(const float2* a, float2* X){
    float2 t0 = cadd(a[0], a[4]), t1 = cadd(a[1], a[5]);
    float2 t2 = cadd(a[2], a[6]), t3 = cadd(a[3], a[7]);
    float2 u0 = csub(a[0], a[4]);
    float2 u1 = mul_w81(csub(a[1], a[5]));
    float2 u2 = mul_mi (csub(a[2], a[6]));
    float2 u3 = mul_w83(csub(a[3], a[7]));
    float2 s0 = cadd(t0, t2), s1 = cadd(t1, t3);
    float2 d0 = csub(t0, t2), d1 = mul_mi(csub(t1, t3));
    float2 e0 = cadd(u0, u2), e1 = cadd(u1, u3);
    float2 f0 = csub(u0, u2), f1 = mul_mi(csub(u1, u3));
    X[0] = cadd(s0, s1); X[4] = csub(s0, s1);
    X[2] = cadd(d0, d1); X[6] = csub(d0, d1);
    X[1] = cadd(e0, e1); X[5] = csub(e0, e1);
    X[3] = cadd(f0, f1); X[7] = csub(f0, f1);
}

// stage 1: a[p] = x[t + 64p] -> y_q[t] = DFT8_p(a) * W512^{tq}, stored at 72q+t
__device__ __forceinline__ void fft_stage1(const float2* a, int t, float* sre, float* sim){
    float2 b[8];
    dft8(a, b);
    float ang = -6.2831853071795864f * (float)t / 512.0f;
    float2 w1; sincosf(ang, &w1.y, &w1.x);
    sre[t] = b[0].x; sim[t] = b[0].y;
    float2 wp = w1;
#pragma unroll
    for (int q = 1; q < 8; q++){
        float2 c = cmul(b[q], wp);
        sre[72*q + t] = c.x; sim[72*q + t] = c.y;
        wp = cmul(wp, w1);
    }
}

// stages 2+3: consumes y in shared, returns X[w] at ky = ky0 + 64w
__device__ __forceinline__ void fft_stage23(float* sre, float* sim, int t,
                                            float2* X, int* ky0_out){
    const int q = t >> 3, u = t & 7;
    float2 a[8], b[8];
#pragma unroll
    for (int v = 0; v < 8; v++){
        int idx = 72*q + u + 8*v;
        a[v] = make_float2(sre[idx], sim[idx]);
    }
    dft8(a, b);
    float ang = -6.2831853071795864f * (float)u / 64.0f;
    float2 w1; sincosf(ang, &w1.y, &w1.x);
    __syncwarp();
    {   // r = 0 (no twiddle)
        int idx = 72*q + (u ^ ((2*q) & 7));
        sre[idx] = b[0].x; sim[idx] = b[0].y;
    }
    float2 wp = w1;
#pragma unroll
    for (int r = 1; r < 8; r++){
        float2 c = cmul(b[r], wp);
        int swz = (2*q + (r >> 2)) & 7;
        int idx = 72*q + 8*r + (u ^ swz);
        sre[idx] = c.x; sim[idx] = c.y;
        wp = cmul(wp, w1);
    }
    __syncwarp();
    const int r3 = u;
    const int swz = (2*q + (r3 >> 2)) & 7;
#pragma unroll
    for (int uu = 0; uu < 8; uu++){
        int idx = 72*q + 8*r3 + (uu ^ swz);
        a[uu] = make_float2(sre[idx], sim[idx]);
    }
    dft8(a, X);
    *ky0_out = q + 8*r3;
}

// ---------------- K1: T-mean + packed row-pair FFT + Hermitian split ---------
__global__ __launch_bounds__(256) void k_mean_rowfft(const float* __restrict__ in){
    __shared__ float sre[4][584], sim[4][584];
    const int tid  = threadIdx.x;
    const int team = tid >> 6;
    const int t    = tid & 63;
    const int b    = blockIdx.x >> 6;
    const int hp   = ((blockIdx.x & 63) << 2) + team;    // row pair 0..255

    const float* base = in + ((size_t)b * NT * N512 + 2 * hp) * N512;
    float2 a[8];
#pragma unroll
    for (int p = 0; p < 8; p++) a[p] = make_float2(0.f, 0.f);
#pragma unroll
    for (int tt = 0; tt < NT; tt++){
        const float* pe = base + (size_t)tt * (N512 * N512);
#pragma unroll
        for (int p = 0; p < 8; p++){
            a[p].x += pe[t + 64*p];            // even row -> re
            a[p].y += pe[N512 + t + 64*p];     // odd row  -> im
        }
    }
#pragma unroll
    for (int p = 0; p < 8; p++){ a[p].x *= 0.125f; a[p].y *= 0.125f; }

    fft_stage1(a, t, sre[team], sim[team]);
    __syncthreads();
    float2 X[8]; int ky0;
    fft_stage23(sre[team], sim[team], t, X, &ky0);
    __syncthreads();
#pragma unroll
    for (int w = 0; w < 8; w++){
        sre[team][ky0 + 72*w] = X[w].x;        // = FPAD(ky0 + 64w)
        sim[team][ky0 + 72*w] = X[w].y;
    }
    __syncthreads();

    // Hermitian split: Z = Fe + i*Fo
    float2* oute = g_fft + ((size_t)b * N512 + 2 * hp) * RS;
    float2* outo = oute + RS;
    for (int k = t; k <= 256; k += 64){
        int m = (N512 - k) & (N512 - 1);
        float2 zk = make_float2(sre[team][FPAD(k)], sim[team][FPAD(k)]);
        float2 zm = make_float2(sre[team][FPAD(m)], sim[team][FPAD(m)]);
        oute[k] = make_float2(0.5f*(zk.x + zm.x), 0.5f*(zk.y - zm.y));
        outo[k] = make_float2(0.5f*(zk.y + zm.y), 0.5f*(zm.x - zk.x));
    }
}

// ---------------- K2: column FFT (4 cols/block) + radial binning -------------
__global__ __launch_bounds__(256) void k_colfft_bin(){
    __shared__ float sre[4][584], sim[4][584];
    __shared__ float pb[256], pc[256];
    const int tid = threadIdx.x;
    const int b   = blockIdx.x / 65;
    const int g   = blockIdx.x % 65;
    const int kx0 = g << 2;

    pb[tid] = 0.f; pc[tid] = 0.f;

    // coop load: 512 rows x 4 columns; full 32B sectors, each element read once
    const float2* src = g_fft + (size_t)b * (N512 * RS);
#pragma unroll
    for (int k = 0; k < 8; k++){
        int idx = tid + (k << 8);
        int row = idx >> 2, c = idx & 3;
        int kx  = kx0 + c;
        float2 v = (kx <= 256) ? src[(size_t)row * RS + kx] : make_float2(0.f, 0.f);
        sre[c][FPAD(row)] = v.x; sim[c][FPAD(row)] = v.y;
    }
    __syncthreads();

    const int team = tid >> 6, t = tid & 63;
    float2 a[8];
#pragma unroll
    for (int p = 0; p < 8; p++)
        a[p] = make_float2(sre[team][t + 72*p], sim[team][t + 72*p]);  // FPAD(t+64p)
    fft_stage1(a, t, sre[team], sim[team]);     // in-place safe: slot set {72j+t} per thread
    __syncthreads();
    float2 X[8]; int ky0;
    fft_stage23(sre[team], sim[team], t, X, &ky0);

    const int kx = kx0 + team;
    if (kx <= 256){
        float wgt = (kx == 0 || kx == 256) ? 1.f : 2.f;   // mirror column folded in
        int   dx  = kx - 256;
        float fdx2 = (float)(dx * dx);
        const bool cblk = (b == 0);
#pragma unroll
        for (int w = 0; w < 8; w++){
            int   ky = ky0 + (w << 6);
            float p  = wgt * (X[w].x * X[w].x + X[w].y * X[w].y);
            int   dy = ky - 256;
            int   rr = (int)__fsqrt_rn((float)(dy * dy) + fdx2);
            if (rr < 256){
                atomicAdd(&pb[rr], p);
                if (cblk) atomicAdd(&pc[rr], wgt);
            }
        }
    }
    __syncthreads();
    g_part[blockIdx.x * 256 + tid] = pb[tid];       // coalesced 1KB per block
    if (b == 0) g_cnt[g * 256 + tid] = pc[tid];
}

// ------- K3: per-bin reduce + last-block loss (single launch) -------
__global__ __launch_bounds__(256) void k_reduce_final(float* __restrict__ out){
    __shared__ float red[256];
    __shared__ int   s_last;
    __shared__ float s_gs, s_rs;
    const int bin = blockIdx.x, tid = threadIdx.x;

    float s = 0.f;
    for (int blk = tid; blk < K2_BLOCKS; blk += 256)
        s += g_part[blk * 256 + bin];
    red[tid] = s; __syncthreads();
    for (int o = 128; o > 0; o >>= 1){ if (tid < o) red[tid] += red[tid + o]; __syncthreads(); }
    float segv = red[0];
    __syncthreads();

    red[tid] = (tid < 65) ? g_cnt[tid * 256 + bin] : 0.f;
    __syncthreads();
    for (int o = 128; o > 0; o >>= 1){ if (tid < o) red[tid] += red[tid + o]; __syncthreads(); }

    if (tid == 0){
        g_seg2[bin] = segv;
        g_cnt2[bin] = red[0];
        __threadfence();
        unsigned old = atomicAdd(&g_arrive, 1u);
        s_last = (old == 255u) ? 1 : 0;
    }
    __syncthreads();
    if (!s_last) return;
    if (tid == 0) g_arrive = 0;          // reset for next replay

    volatile float* vseg = g_seg2;
    volatile float* vcnt = g_cnt2;
    float gen = 0.f, refv = 0.f;
    if (tid >= 1){
        float cr    = vcnt[tid];
        float denom = fmaxf(cr, 1.0f) * (float)NB;
        gen  = (cr > 0.f) ? vseg[tid] / denom : 0.0f;
        refv = powf((float)tid, -5.0f / 3.0f);
    }

    red[tid] = gen; __syncthreads();
    for (int o = 128; o > 0; o >>= 1){ if (tid < o) red[tid] += red[tid + o]; __syncthreads(); }
    if (tid == 0) s_gs = red[0] + 1e-8f;
    __syncthreads();
    red[tid] = refv; __syncthreads();
    for (int o = 128; o > 0; o >>= 1){ if (tid < o) red[tid] += red[tid + o]; __syncthreads(); }
    if (tid == 0) s_rs = red[0] + 1e-8f;
    __syncthreads();

    float d = (tid >= 1) ? (gen / s_gs - refv / s_rs) : 0.f;
    red[tid] = d * d; __syncthreads();
    for (int o = 128; o > 0; o >>= 1){ if (tid < o) red[tid] += red[tid + o]; __syncthreads(); }
    if (tid == 0) out[0] = red[0] / 255.0f;
}

extern "C" void kernel_launch(void* const* d_in, const int* in_sizes, int n_in,
                              void* d_out, int out_size) {
    (void)in_sizes; (void)n_in; (void)out_size;
    const float* in  = (const float*)d_in[0];
    float*       out = (float*)d_out;

    k_mean_rowfft<<<NB * 64, 256>>>(in);
    k_colfft_bin<<<K2_BLOCKS, 256>>>();
    k_reduce_final<<<256, 256>>>(out);
}